// round 17
// baseline (speedup 1.0000x reference)
#include <cuda_runtime.h>
#include <cstdint>

#define BATCH  32
#define SEQ    512
#define LAB    64
#define START_ 61
#define STOP_  62
#define CH     32

#define FMA2(d,a,b,c)  asm("fma.rn.f32x2 %0, %1, %2, %3;" : "=l"(d) : "l"(a), "l"(b), "l"(c))
#define ADD2(d,a,b)    asm("add.rn.f32x2 %0, %1, %2;"     : "=l"(d) : "l"(a), "l"(b))
#define PACK2(d,lo,hi) asm("mov.b64 %0, {%1, %2};"        : "=l"(d) : "f"(lo), "f"(hi))
#define UNPACK2(lo,hi,s) asm("mov.b64 {%0, %1}, %2;"      : "=f"(lo), "=f"(hi) : "l"(s))
#define CPA(dst,src) asm volatile("cp.async.cg.shared.global [%0], [%1], 16;\n" :: "r"(dst), "l"(src))
#define CPC() asm volatile("cp.async.commit_group;\n")
#define CPW1() asm volatile("cp.async.wait_group 1;\n")
#define CPW0() asm volatile("cp.async.wait_group 0;\n")

// 64-thread chunk prefetch: 8 KB = 8 x (64 thr x 16 B)
#define PREFETCH(cc) do {                                                       \
    const float* _src = encb + (size_t)(cc) * CH * LAB + tid * 4;               \
    uint32_t _dst = (uint32_t)__cvta_generic_to_shared(&e_sh[(cc) & 1][tid*4]); \
    CPA(_dst,        _src);         CPA(_dst + 1024, _src + 256);               \
    CPA(_dst + 2048, _src + 512);   CPA(_dst + 3072, _src + 768);               \
    CPA(_dst + 4096, _src + 1024);  CPA(_dst + 5120, _src + 1280);              \
    CPA(_dst + 6144, _src + 1536);  CPA(_dst + 7168, _src + 1792);              \
    CPC();                                                                      \
} while (0)

// dual-column half-i dot: 8 LDS.128 over my 32-row half, 32 FMA2 (2 cols),
// partials merged with the xor-1 partner after the macro.
#define DOTH(PP, QA, QB, P0B)                                                   \
    const ulonglong2* pv = reinterpret_cast<const ulonglong2*>((PP) + g * 32);  \
    ulonglong2 v0 = pv[0], v1 = pv[1], v2 = pv[2], v3 = pv[3];                  \
    ulonglong2 v4 = pv[4], v5 = pv[5], v6 = pv[6], v7 = pv[7];                  \
    unsigned int P0B = (unsigned int)v0.x;                                      \
    unsigned long long aA0 = 0, aA1 = 0, aB0 = 0, aB1 = 0;                      \
    FMA2(aA0, v0.x, EA[ 0], aA0); FMA2(aB0, v0.x, EB[ 0], aB0);                 \
    FMA2(aA1, v0.y, EA[ 1], aA1); FMA2(aB1, v0.y, EB[ 1], aB1);                 \
    FMA2(aA0, v1.x, EA[ 2], aA0); FMA2(aB0, v1.x, EB[ 2], aB0);                 \
    FMA2(aA1, v1.y, EA[ 3], aA1); FMA2(aB1, v1.y, EB[ 3], aB1);                 \
    FMA2(aA0, v2.x, EA[ 4], aA0); FMA2(aB0, v2.x, EB[ 4], aB0);                 \
    FMA2(aA1, v2.y, EA[ 5], aA1); FMA2(aB1, v2.y, EB[ 5], aB1);                 \
    FMA2(aA0, v3.x, EA[ 6], aA0); FMA2(aB0, v3.x, EB[ 6], aB0);                 \
    FMA2(aA1, v3.y, EA[ 7], aA1); FMA2(aB1, v3.y, EB[ 7], aB1);                 \
    FMA2(aA0, v4.x, EA[ 8], aA0); FMA2(aB0, v4.x, EB[ 8], aB0);                 \
    FMA2(aA1, v4.y, EA[ 9], aA1); FMA2(aB1, v4.y, EB[ 9], aB1);                 \
    FMA2(aA0, v5.x, EA[10], aA0); FMA2(aB0, v5.x, EB[10], aB0);                 \
    FMA2(aA1, v5.y, EA[11], aA1); FMA2(aB1, v5.y, EB[11], aB1);                 \
    FMA2(aA0, v6.x, EA[12], aA0); FMA2(aB0, v6.x, EB[12], aB0);                 \
    FMA2(aA1, v6.y, EA[13], aA1); FMA2(aB1, v6.y, EB[13], aB1);                 \
    FMA2(aA0, v7.x, EA[14], aA0); FMA2(aB0, v7.x, EB[14], aB0);                 \
    FMA2(aA1, v7.y, EA[15], aA1); FMA2(aB1, v7.y, EB[15], aB1);                 \
    unsigned long long sA, sBv;                                                 \
    ADD2(sA, aA0, aA1); ADD2(sBv, aB0, aB1);                                    \
    float _al, _ah, _bl, _bh;                                                   \
    UNPACK2(_al, _ah, sA); UNPACK2(_bl, _bh, sBv);                              \
    float QA = _al + _ah;                                                       \
    float QB = _bl + _bh;                                                       \
    QA += __shfl_xor_sync(0xffffffffu, QA, 1);                                  \
    QB += __shfl_xor_sync(0xffffffffu, QB, 1)

// chains per batch: 0=x(seg1) 1=f2 2=f3 3=f4 4=g2 5=g3 6=g4 7=y(seg5)
__device__ float g_v[8][BATCH][LAB];
__device__ int   g_mi8[8][BATCH];
__device__ int   g_cnt[BATCH];     // never reset; +8 per launch; (old&7)==7 -> combiner

__global__ __launch_bounds__(64, 1)
void crf_fused_kernel(const float* __restrict__ enc,   // [B,S,L]
                      const float* __restrict__ T,     // [L,L]
                      const int*   __restrict__ lens,  // [B]
                      const int*   __restrict__ tags,  // [B,S]
                      float*       __restrict__ out)   // [2*B]
{
    const int tid = threadIdx.x;

    // ================= LABELED blocks: 256..287 =================
    if (blockIdx.x >= 8 * BATCH) {
        const int b   = blockIdx.x - 8 * BATCH;
        const int len = lens[b];
        const float* encb = enc + (size_t)b * SEQ * LAB;
        const int*   tagb = tags + b * SEQ;
        __shared__ float lred[2];

        float lsum = 0.0f;
        for (int t = 1 + tid; t < len; t += 64) {
            int tg = tagb[t], tp = tagb[t - 1];
            lsum += T[tp * LAB + tg] + encb[(size_t)t * LAB + tg];
        }
        #pragma unroll
        for (int m = 16; m; m >>= 1)
            lsum += __shfl_xor_sync(0xffffffffu, lsum, m);
        if ((tid & 31) == 0) lred[tid >> 5] = lsum;
        __syncthreads();
        if (tid == 0) {
            int t0g = tagb[0];
            int eg  = tagb[len - 1];
            out[BATCH + b] = lred[0] + lred[1]
                           + T[START_ * LAB + t0g] + encb[t0g]
                           + T[eg * LAB + STOP_];
        }
        return;
    }

    // ================= CHAIN blocks: 0..255 =================
    // thread (j2 = tid>>1, g = tid&1): columns {2j2, 2j2+1}, i-half [32g, 32g+32)
    __shared__ __align__(16) float e_sh[2][CH * LAB];
    __shared__ __align__(16) float p_sh[2][LAB];
    __shared__ float du[14];
    __shared__ int win_sh;

    const int b   = blockIdx.x >> 3;
    const int k   = blockIdx.x & 7;       // chain id 0..7
    const int len = lens[b];
    const int n   = len - 1;
    int sB[6];
    #pragma unroll
    for (int i = 0; i <= 5; ++i) sB[i] = (i * n) / 5;
    const float* encb = enc + (size_t)b * SEQ * LAB;
    const int*   tagb = tags + b * SEQ;

    const int j2 = tid >> 1;
    const int g  = tid & 1;
    const int c0 = 2 * j2, c1 = 2 * j2 + 1;

    int Mi = 0;
    int par_out;

    if (k <= 3) {
        // ---- FORWARD chains: p <- D_u E^T p over seg k+1 = (sB[k], sB[k+1]] ----
        const int t0 = sB[k] + 1;
        const int t1 = sB[k + 1];
        const int cc0 = t0 >> 5, cc1 = t1 >> 5;
        PREFETCH(cc0);
        if (cc0 < cc1) PREFETCH(cc0 + 1);

        unsigned long long EA[16], EB[16];   // E cols c0,c1 over rows [32g,32g+32)
        #pragma unroll
        for (int kk = 0; kk < 16; ++kk) {
            int i = g * 32 + 2 * kk;
            float a0 = __expf(T[i * LAB + c0]);
            float a1 = __expf(T[(i + 1) * LAB + c0]);
            float b0 = __expf(T[i * LAB + c1]);
            float b1 = __expf(T[(i + 1) * LAB + c1]);
            PACK2(EA[kk], a0, a1);
            PACK2(EB[kk], b0, b1);
        }

        if (cc0 < cc1) CPW1(); else CPW0();
        __syncthreads();
        if (g == 0) {
            if (k == 0) {
                p_sh[0][c0] = __expf(T[START_ * LAB + c0] + e_sh[0][c0]);
                p_sh[0][c1] = __expf(T[START_ * LAB + c1] + e_sh[0][c1]);
            } else {
                *reinterpret_cast<float2*>(&p_sh[(t0 - 1) & 1][c0]) =
                    make_float2(1.0f, 1.0f);
            }
        }
        __syncthreads();

        int t = t0;
        for (int c = cc0; c <= cc1; ++c) {
            if (c > cc0) {
                if (c < cc1) { PREFETCH(c + 1); CPW1(); } else CPW0();
                __syncthreads();
            }
            const float* eb = e_sh[c & 1];
            const int ttend = min((c + 1) * CH - 1, t1);
            #pragma unroll 2
            for (; t <= ttend; ++t) {
                const float* pp = &p_sh[(t - 1) & 1][0];
                const int ro = (t - c * CH) * LAB;
                DOTH(pp, qA, qB, p0b);
                if (g == 0) {
                    int   e0 = (int)((p0b >> 23) & 255u) - 127;
                    float sc = __int_as_float((127 - e0) << 23);
                    Mi += e0;
                    float uA = __expf(eb[ro + c0]);
                    float uB = __expf(eb[ro + c1]);
                    *reinterpret_cast<float2*>(&p_sh[t & 1][c0]) =
                        make_float2(qA * uA * sc, qB * uB * sc);
                }
                __syncthreads();
            }
        }
        par_out = t1 & 1;
    } else {
        // ---- BACKWARD chains: w <- D_u E w over seg sg = (sB[sg-1], sB[sg]] ----
        const int sg = k - 2;                          // 2,3,4,5
        const int s_init = sB[sg];
        const int s_end  = sB[sg - 1];
        const int s1 = s_init - 1, s0 = s_end;
        const int chi = s1 >> 5, clo = s0 >> 5;
        PREFETCH(chi);
        if (chi > clo) PREFETCH(chi - 1);

        unsigned long long EA[16], EB[16];   // E rows c0,c1 over cols [32g,32g+32)
        #pragma unroll
        for (int kk = 0; kk < 16; ++kk) {
            int i = g * 32 + 2 * kk;
            float a0 = __expf(T[c0 * LAB + i]);
            float a1 = __expf(T[c0 * LAB + i + 1]);
            float b0 = __expf(T[c1 * LAB + i]);
            float b1 = __expf(T[c1 * LAB + i + 1]);
            PACK2(EA[kk], a0, a1);
            PACK2(EB[kk], b0, b1);
        }

        if (g == 0) {
            float uiA = __expf(encb[(size_t)s_init * LAB + c0]);
            float uiB = __expf(encb[(size_t)s_init * LAB + c1]);
            if (sg == 5) {
                uiA *= __expf(T[c0 * LAB + STOP_]);    // y: c * u_n
                uiB *= __expf(T[c1 * LAB + STOP_]);
            }
            *reinterpret_cast<float2*>(&p_sh[(s1 + 1) & 1][c0]) =
                make_float2(uiA, uiB);
        }
        if (chi > clo) CPW1(); else CPW0();
        __syncthreads();

        int s = s1;
        for (int c = chi; c >= clo; --c) {
            if (c < chi) {
                if (c > clo) { PREFETCH(c - 1); CPW1(); } else CPW0();
                __syncthreads();
            }
            const float* eb = e_sh[c & 1];
            const int slo = max(s0, c * CH);
            #pragma unroll 2
            for (; s >= slo; --s) {
                const float* pp = &p_sh[(s + 1) & 1][0];
                const int ro = (s - c * CH) * LAB;
                DOTH(pp, qA, qB, p0b);
                if (g == 0) {
                    int   e0 = (int)((p0b >> 23) & 255u) - 127;
                    float sc = __int_as_float((127 - e0) << 23);
                    Mi += e0;
                    float uA = __expf(eb[ro + c0]);
                    float uB = __expf(eb[ro + c1]);
                    float usA = (s == s0) ? sc : uA * sc;   // boundary: E only
                    float usB = (s == s0) ? sc : uB * sc;
                    *reinterpret_cast<float2*>(&p_sh[s & 1][c0]) =
                        make_float2(qA * usA, qB * usB);
                }
                __syncthreads();
            }
        }
        par_out = s0 & 1;
    }

    g_v[k][b][tid] = p_sh[par_out][tid];
    if (tid == 0) g_mi8[k][b] = Mi;

    // ---- last-arriver combine (unlabeled output) ----
    __threadfence();
    __syncthreads();
    if (tid == 0) {
        int old = atomicAdd(&g_cnt[b], 1);
        win_sh = ((old & 7) == 7);         // 8th of the group this launch
    }
    __syncthreads();
    if (win_sh) {
        float xv  = __ldcg(&g_v[0][b][tid]);
        float f2v = __ldcg(&g_v[1][b][tid]);
        float f3v = __ldcg(&g_v[2][b][tid]);
        float f4v = __ldcg(&g_v[3][b][tid]);
        float g2v = __ldcg(&g_v[4][b][tid]);
        float g3v = __ldcg(&g_v[5][b][tid]);
        float g4v = __ldcg(&g_v[6][b][tid]);
        float yv  = __ldcg(&g_v[7][b][tid]);
        float d1 = yv  * f4v;    // c^T M5 f4
        float d2 = g4v * f3v;
        float d3 = g3v * f2v;
        float d4 = g2v * xv;     // g2^T M1 p0
        float d5 = f2v, d6 = f3v, d7 = f4v;
        #pragma unroll
        for (int m = 16; m; m >>= 1) {
            d1 += __shfl_xor_sync(0xffffffffu, d1, m);
            d2 += __shfl_xor_sync(0xffffffffu, d2, m);
            d3 += __shfl_xor_sync(0xffffffffu, d3, m);
            d4 += __shfl_xor_sync(0xffffffffu, d4, m);
            d5 += __shfl_xor_sync(0xffffffffu, d5, m);
            d6 += __shfl_xor_sync(0xffffffffu, d6, m);
            d7 += __shfl_xor_sync(0xffffffffu, d7, m);
        }
        if (tid == 0) {
            du[0]=d1; du[1]=d2; du[2]=d3; du[3]=d4; du[4]=d5; du[5]=d6; du[6]=d7;
        }
        if (tid == 32) {
            du[7]=d1; du[8]=d2; du[9]=d3; du[10]=d4; du[11]=d5; du[12]=d6; du[13]=d7;
        }
        __syncthreads();
        if (tid == 0) {
            float D1 = du[0] + du[7];
            float D2 = du[1] + du[8];
            float D3 = du[2] + du[9];
            float D4 = du[3] + du[10];
            float S2 = du[4] + du[11];
            float S3 = du[5] + du[12];
            float S4 = du[6] + du[13];
            int mtot = __ldcg(&g_mi8[0][b]) + __ldcg(&g_mi8[4][b])
                     + __ldcg(&g_mi8[5][b]) + __ldcg(&g_mi8[6][b])
                     + __ldcg(&g_mi8[7][b]);
            double lg = (double)logf(D1) + (double)logf(D2)
                      + (double)logf(D3) + (double)logf(D4)
                      - (double)logf(S2) - (double)logf(S3) - (double)logf(S4);
            out[b] = (float)((double)mtot * 0.6931471805599453 + lg);
        }
    }
}

extern "C" void kernel_launch(void* const* d_in, const int* in_sizes, int n_in,
                              void* d_out, int out_size)
{
    const float* enc  = (const float*)d_in[0];   // encoder_scores [32,512,64]
    const float* T    = (const float*)d_in[1];   // transition [64,64]
    const int*   lens = (const int*)  d_in[2];   // word_seq_lens [32]
    const int*   tags = (const int*)  d_in[3];   // tags [32,512]
    float* out = (float*)d_out;                  // [64]: unlabeled(32) ++ labeled(32)

    crf_fused_kernel<<<9 * BATCH, 64>>>(enc, T, lens, tags, out);
}